// round 1
// baseline (speedup 1.0000x reference)
#include <cuda_runtime.h>
#include <math.h>

// ---------------------------------------------------------------------------
// PromptBlock: CLIP transformer block with prompt-prefixed KV.
// B=16, N=1024, D=768, H=12, HD=64, P=16, FF=3072, fp32 throughout.
// Round 1: correctness-first fp32 baseline (tiled SGEMM + flash attention).
// ---------------------------------------------------------------------------

namespace {
constexpr int B_  = 16;
constexpr int N_  = 1024;
constexpr int D_  = 768;
constexpr int H_  = 12;
constexpr int HD_ = 64;
constexpr int P_  = 16;
constexpr int FF_ = 3072;
constexpr int M_  = B_ * N_;          // 16384 token rows
constexpr int KVLEN_ = P_ + N_;       // 1040
constexpr int ATTN_SMEM_FLOATS = 4096 + 3 * 4160;   // Qs[64*64] + Ks/Vs/Ps[64*65]
constexpr int ATTN_SMEM_BYTES  = ATTN_SMEM_FLOATS * 4;  // 66304
}

// Scratch buffers (static __device__ — no allocations allowed).
__device__ float g_h[M_ * D_];                 // LN output (reused for LN1 and LN2)
__device__ float g_qkv[(size_t)M_ * 3 * D_];   // QKV projections
__device__ float g_o[M_ * D_];                 // attention output (pre out-proj)
__device__ float g_x1[M_ * D_];                // x + attn branch
__device__ float g_m[(size_t)M_ * FF_];        // MLP hidden

// ---------------------------------------------------------------------------
// LayerNorm: one block per row of 768, 256 threads x 3 elements.
// ---------------------------------------------------------------------------
__global__ void __launch_bounds__(256) ln_kernel(
    const float* __restrict__ x, const float* __restrict__ gma,
    const float* __restrict__ bta, float* __restrict__ out)
{
    int row = blockIdx.x;
    const float* xr = x + (size_t)row * D_;
    float* orow = out + (size_t)row * D_;
    int t = threadIdx.x;

    float v0 = xr[t], v1 = xr[t + 256], v2 = xr[t + 512];
    float s  = v0 + v1 + v2;
    float s2 = v0 * v0 + v1 * v1 + v2 * v2;
#pragma unroll
    for (int m = 16; m; m >>= 1) {
        s  += __shfl_xor_sync(0xffffffffu, s,  m);
        s2 += __shfl_xor_sync(0xffffffffu, s2, m);
    }
    __shared__ float ws[8], ws2[8], stat[2];
    int w = t >> 5;
    if ((t & 31) == 0) { ws[w] = s; ws2[w] = s2; }
    __syncthreads();
    if (t == 0) {
        float a = 0.f, a2 = 0.f;
#pragma unroll
        for (int i = 0; i < 8; i++) { a += ws[i]; a2 += ws2[i]; }
        float mu  = a * (1.0f / D_);
        float var = a2 * (1.0f / D_) - mu * mu;
        stat[0] = mu;
        stat[1] = rsqrtf(var + 1e-5f);
    }
    __syncthreads();
    float mu = stat[0], rs = stat[1];
    orow[t]       = (v0 - mu) * rs * gma[t]       + bta[t];
    orow[t + 256] = (v1 - mu) * rs * gma[t + 256] + bta[t + 256];
    orow[t + 512] = (v2 - mu) * rs * gma[t + 512] + bta[t + 512];
}

// ---------------------------------------------------------------------------
// SGEMM: C[M,N] = A[M,K] @ B[N,K]^T + bias (+ residual / QuickGELU).
// 128x128 tile, BK=8, 256 threads, 8x8 per-thread register tile.
// MODE: 0 = bias, 1 = bias + residual, 2 = bias + QuickGELU.
// M,N multiples of 128; K multiple of 8 (always true for this problem).
// ---------------------------------------------------------------------------
template <int MODE>
__global__ void __launch_bounds__(256) gemm_kernel(
    const float* __restrict__ A, const float* __restrict__ Bm,
    const float* __restrict__ bias, const float* __restrict__ res,
    float* __restrict__ C, int M, int N, int K)
{
    __shared__ float As[8][128];
    __shared__ float Bs[8][128];

    int t = threadIdx.x;
    int col0 = blockIdx.x * 128;
    int row0 = blockIdx.y * 128;

    int lr = t >> 1;            // 0..127: tile row (A) / tile col (B)
    int lk = (t & 1) * 4;       // 0 or 4: k sub-offset
    const float* Ap = A  + (size_t)(row0 + lr) * K + lk;
    const float* Bp = Bm + (size_t)(col0 + lr) * K + lk;

    int tx = t & 15, ty = t >> 4;

    float acc[8][8];
#pragma unroll
    for (int i = 0; i < 8; i++)
#pragma unroll
        for (int j = 0; j < 8; j++) acc[i][j] = 0.f;

    for (int k0 = 0; k0 < K; k0 += 8) {
        float4 av = *(const float4*)(Ap + k0);
        float4 bv = *(const float4*)(Bp + k0);
        As[lk + 0][lr] = av.x; As[lk + 1][lr] = av.y;
        As[lk + 2][lr] = av.z; As[lk + 3][lr] = av.w;
        Bs[lk + 0][lr] = bv.x; Bs[lk + 1][lr] = bv.y;
        Bs[lk + 2][lr] = bv.z; Bs[lk + 3][lr] = bv.w;
        __syncthreads();
#pragma unroll
        for (int kk = 0; kk < 8; kk++) {
            float4 a0 = *(const float4*)&As[kk][ty * 8];
            float4 a1 = *(const float4*)&As[kk][ty * 8 + 4];
            float4 b0 = *(const float4*)&Bs[kk][tx * 8];
            float4 b1 = *(const float4*)&Bs[kk][tx * 8 + 4];
            float a[8] = {a0.x, a0.y, a0.z, a0.w, a1.x, a1.y, a1.z, a1.w};
            float b[8] = {b0.x, b0.y, b0.z, b0.w, b1.x, b1.y, b1.z, b1.w};
#pragma unroll
            for (int i = 0; i < 8; i++)
#pragma unroll
                for (int j = 0; j < 8; j++)
                    acc[i][j] += a[i] * b[j];
        }
        __syncthreads();
    }

    float bfrag[8];
#pragma unroll
    for (int j = 0; j < 8; j++) bfrag[j] = bias[col0 + tx * 8 + j];

#pragma unroll
    for (int i = 0; i < 8; i++) {
        int r = row0 + ty * 8 + i;
        float* crow = C + (size_t)r * N + col0 + tx * 8;
        const float* rrow = (MODE == 1) ? (res + (size_t)r * N + col0 + tx * 8) : nullptr;
#pragma unroll
        for (int j = 0; j < 8; j++) {
            float v = acc[i][j] + bfrag[j];
            if (MODE == 1) v += rrow[j];
            if (MODE == 2) v = v / (1.f + expf(-1.702f * v));   // QuickGELU
            crow[j] = v;
        }
    }
}

// ---------------------------------------------------------------------------
// Flash attention with prompt-prefixed KV.
//   grid = (N/64, H, B), 256 threads.
//   BQ=64, BK=64, 17 key tiles (last tile: 16 valid keys), online softmax.
//   Thread (rg,cg) owns a 4x4 S tile and a 4x4 O tile; P staged through smem.
// ---------------------------------------------------------------------------
__global__ void __launch_bounds__(256) attn_kernel(
    const float* __restrict__ qkv, const float* __restrict__ prompt,
    float* __restrict__ o)
{
    extern __shared__ float sm_attn[];
    float* Qs = sm_attn;                  // [64][64]
    float* Ks = sm_attn + 4096;           // [64][65]
    float* Vs = sm_attn + 4096 + 4160;    // [64][65]
    float* Ps = sm_attn + 4096 + 2 * 4160;// [64][65]

    int q0 = blockIdx.x * 64;
    int h  = blockIdx.y;
    int b  = blockIdx.z;
    int t  = threadIdx.x;
    int rg = t >> 4;     // row group: 4 rows each
    int cg = t & 15;     // col group: 4 cols each

    // Load Q tile [64 x 64]
    for (int i = t; i < 1024; i += 256) {
        int r  = i >> 4;
        int d4 = (i & 15) * 4;
        float4 v = *(const float4*)(qkv + (size_t)(b * N_ + q0 + r) * (3 * D_) + h * 64 + d4);
        *(float4*)&Qs[r * 64 + d4] = v;
    }

    float m_i[4], l_i[4], O[4][4];
#pragma unroll
    for (int i = 0; i < 4; i++) {
        m_i[i] = -1e30f;
        l_i[i] = 0.f;
#pragma unroll
        for (int j = 0; j < 4; j++) O[i][j] = 0.f;
    }

    for (int kt = 0; kt < 17; kt++) {
        int j0 = kt * 64;
        // Load K/V tile (prompt rows for j<16, token rows after, zeros past 1040).
        for (int i = t; i < 1024; i += 256) {
            int r  = i >> 4;
            int d4 = (i & 15) * 4;
            int j  = j0 + r;
            float4 kv, vv;
            if (j < P_) {
                const float* pb = prompt + ((((size_t)b * 2 + 0) * P_ + j) * H_ + h) * 64 + d4;
                kv = *(const float4*)pb;
                vv = *(const float4*)(pb + (size_t)P_ * H_ * 64);   // c=1 plane
            } else if (j < KVLEN_) {
                const float* base = qkv + (size_t)(b * N_ + (j - P_)) * (3 * D_) + h * 64 + d4;
                kv = *(const float4*)(base + D_);         // K plane
                vv = *(const float4*)(base + 2 * D_);     // V plane
            } else {
                kv = make_float4(0.f, 0.f, 0.f, 0.f);
                vv = kv;
            }
            Ks[r * 65 + d4 + 0] = kv.x; Ks[r * 65 + d4 + 1] = kv.y;
            Ks[r * 65 + d4 + 2] = kv.z; Ks[r * 65 + d4 + 3] = kv.w;
            Vs[r * 65 + d4 + 0] = vv.x; Vs[r * 65 + d4 + 1] = vv.y;
            Vs[r * 65 + d4 + 2] = vv.z; Vs[r * 65 + d4 + 3] = vv.w;
        }
        __syncthreads();

        // S = Q K^T for this 64x64 tile (4x4 per thread).
        float s[4][4];
#pragma unroll
        for (int i = 0; i < 4; i++)
#pragma unroll
            for (int j = 0; j < 4; j++) s[i][j] = 0.f;

        for (int d = 0; d < 64; d++) {
            float qv[4], kv[4];
#pragma unroll
            for (int i = 0; i < 4; i++) qv[i] = Qs[(rg * 4 + i) * 64 + d];
#pragma unroll
            for (int j = 0; j < 4; j++) kv[j] = Ks[(cg * 4 + j) * 65 + d];
#pragma unroll
            for (int i = 0; i < 4; i++)
#pragma unroll
                for (int j = 0; j < 4; j++)
                    s[i][j] += qv[i] * kv[j];
        }

        // Online softmax update per row.
#pragma unroll
        for (int i = 0; i < 4; i++) {
#pragma unroll
            for (int j = 0; j < 4; j++)
                s[i][j] = (j0 + cg * 4 + j < KVLEN_) ? s[i][j] * 0.125f : -1e30f;

            float mx = fmaxf(fmaxf(s[i][0], s[i][1]), fmaxf(s[i][2], s[i][3]));
#pragma unroll
            for (int msk = 1; msk < 16; msk <<= 1)
                mx = fmaxf(mx, __shfl_xor_sync(0xffffffffu, mx, msk));

            float mn   = fmaxf(m_i[i], mx);
            float corr = expf(m_i[i] - mn);
            float ps   = 0.f;
#pragma unroll
            for (int j = 0; j < 4; j++) {
                float p = expf(s[i][j] - mn);
                s[i][j] = p;
                ps += p;
            }
#pragma unroll
            for (int msk = 1; msk < 16; msk <<= 1)
                ps += __shfl_xor_sync(0xffffffffu, ps, msk);

            l_i[i] = l_i[i] * corr + ps;
            m_i[i] = mn;
#pragma unroll
            for (int j = 0; j < 4; j++) O[i][j] *= corr;
        }

        // Stage P through smem, then O += P @ V.
#pragma unroll
        for (int i = 0; i < 4; i++)
#pragma unroll
            for (int j = 0; j < 4; j++)
                Ps[(rg * 4 + i) * 65 + cg * 4 + j] = s[i][j];
        __syncthreads();

        for (int k = 0; k < 64; k++) {
            float pv[4], vv[4];
#pragma unroll
            for (int i = 0; i < 4; i++) pv[i] = Ps[(rg * 4 + i) * 65 + k];
#pragma unroll
            for (int j = 0; j < 4; j++) vv[j] = Vs[k * 65 + cg * 4 + j];
#pragma unroll
            for (int i = 0; i < 4; i++)
#pragma unroll
                for (int j = 0; j < 4; j++)
                    O[i][j] += pv[i] * vv[j];
        }
        __syncthreads();
    }

    // Normalize and write o[b, q, h*64 + d] in [B,N,D] layout.
#pragma unroll
    for (int i = 0; i < 4; i++) {
        float inv = 1.f / l_i[i];
        int r = q0 + rg * 4 + i;
        float* dst = o + (size_t)(b * N_ + r) * D_ + h * 64 + cg * 4;
#pragma unroll
        for (int j = 0; j < 4; j++) dst[j] = O[i][j] * inv;
    }
}

// ---------------------------------------------------------------------------
// Launch pipeline (graph-capturable: kernel launches + attribute set only).
// ---------------------------------------------------------------------------
extern "C" void kernel_launch(void* const* d_in, const int* in_sizes, int n_in,
                              void* d_out, int out_size)
{
    const float* x      = (const float*)d_in[0];
    const float* prompt = (const float*)d_in[1];
    const float* qkv_w  = (const float*)d_in[2];
    const float* qkv_b  = (const float*)d_in[3];
    const float* out_w  = (const float*)d_in[4];
    const float* out_b  = (const float*)d_in[5];
    const float* ln1_g  = (const float*)d_in[6];
    const float* ln1_b  = (const float*)d_in[7];
    const float* ln2_g  = (const float*)d_in[8];
    const float* ln2_b  = (const float*)d_in[9];
    const float* fc1_w  = (const float*)d_in[10];
    const float* fc1_b  = (const float*)d_in[11];
    const float* fc2_w  = (const float*)d_in[12];
    const float* fc2_b  = (const float*)d_in[13];
    float* out = (float*)d_out;

    void *ph, *pqkv, *po, *px1, *pm;
    cudaGetSymbolAddress(&ph,   g_h);
    cudaGetSymbolAddress(&pqkv, g_qkv);
    cudaGetSymbolAddress(&po,   g_o);
    cudaGetSymbolAddress(&px1,  g_x1);
    cudaGetSymbolAddress(&pm,   g_m);
    float* hbuf   = (float*)ph;
    float* qkvbuf = (float*)pqkv;
    float* obuf   = (float*)po;
    float* x1buf  = (float*)px1;
    float* mbuf   = (float*)pm;

    // 1. h = LN1(x)
    ln_kernel<<<M_, 256>>>(x, ln1_g, ln1_b, hbuf);

    // 2. qkv = h @ qkv_w^T + qkv_b          [16384 x 2304]
    gemm_kernel<0><<<dim3((3 * D_) / 128, M_ / 128), 256>>>(
        hbuf, qkv_w, qkv_b, nullptr, qkvbuf, M_, 3 * D_, D_);

    // 3. o = attention(q, [pk;k], [pv;v])
    cudaFuncSetAttribute(attn_kernel, cudaFuncAttributeMaxDynamicSharedMemorySize,
                         ATTN_SMEM_BYTES);
    attn_kernel<<<dim3(N_ / 64, H_, B_), 256, ATTN_SMEM_BYTES>>>(qkvbuf, prompt, obuf);

    // 4. x1 = x + o @ out_w^T + out_b       [16384 x 768]
    gemm_kernel<1><<<dim3(D_ / 128, M_ / 128), 256>>>(
        obuf, out_w, out_b, x, x1buf, M_, D_, D_);

    // 5. h = LN2(x1)
    ln_kernel<<<M_, 256>>>(x1buf, ln2_g, ln2_b, hbuf);

    // 6. m = QuickGELU(h @ fc1_w^T + fc1_b) [16384 x 3072]
    gemm_kernel<2><<<dim3(FF_ / 128, M_ / 128), 256>>>(
        hbuf, fc1_w, fc1_b, nullptr, mbuf, M_, FF_, D_);

    // 7. out = x1 + m @ fc2_w^T + fc2_b     [16384 x 768]
    gemm_kernel<1><<<dim3(D_ / 128, M_ / 128), 256>>>(
        mbuf, fc2_w, fc2_b, x1buf, out, M_, D_, FF_);
}

// round 4
// speedup vs baseline: 1.7318x; 1.7318x over previous
#include <cuda_runtime.h>
#include <cuda_bf16.h>
#include <cstdint>
#include <math.h>

// ---------------------------------------------------------------------------
// PromptBlock R3: mma.sync bf16 (3-term hi/lo split) GEMMs + fp32 flash attn.
// (tcgen05 is unavailable: harness PTX targets sm_103, not sm_103a.)
// ---------------------------------------------------------------------------

namespace {
constexpr int B_  = 16;
constexpr int N_  = 1024;
constexpr int D_  = 768;
constexpr int H_  = 12;
constexpr int P_  = 16;
constexpr int FF_ = 3072;
constexpr int M_  = B_ * N_;          // 16384
constexpr int KVLEN_ = P_ + N_;       // 1040
constexpr int ATTN_SMEM_BYTES = (4096 + 3 * 4160) * 4;   // 66304

// GEMM tiling
constexpr int BM = 128, BN = 128, BK = 32;
constexpr int STAGES = 4;
constexpr int ROWB = 80;                       // 32 bf16 (64B) + 16B pad
constexpr int TILE_A = BM * ROWB;              // 10240 B
constexpr int STAGE_BYTES = 2 * TILE_A;        // A + B per stage
constexpr int GEMM_SMEM = STAGES * STAGE_BYTES; // 81920 B
}

// ---------------------------------------------------------------------------
// Scratch (__device__ globals; no allocations allowed).
// ---------------------------------------------------------------------------
__device__ __nv_bfloat16 g_hh[M_ * D_], g_hl[M_ * D_];
__device__ float         g_qkv[(size_t)M_ * 3 * D_];
__device__ __nv_bfloat16 g_oh[M_ * D_], g_ol[M_ * D_];
__device__ float         g_x1[M_ * D_];
__device__ __nv_bfloat16 g_mh[(size_t)M_ * FF_], g_ml[(size_t)M_ * FF_];
__device__ __nv_bfloat16 g_w1h[3 * D_ * D_], g_w1l[3 * D_ * D_];
__device__ __nv_bfloat16 g_w2h[D_ * D_],     g_w2l[D_ * D_];
__device__ __nv_bfloat16 g_w3h[FF_ * D_],    g_w3l[FF_ * D_];
__device__ __nv_bfloat16 g_w4h[D_ * FF_],    g_w4l[D_ * FF_];

// ---------------------------------------------------------------------------
// PTX helpers (sm_80-level ISA only — compiles under .target sm_103).
// ---------------------------------------------------------------------------
__device__ __forceinline__ uint32_t smem_u32(const void* p) {
    uint32_t a;
    asm("{ .reg .u64 t; cvta.to.shared.u64 t, %1; cvt.u32.u64 %0, t; }"
        : "=r"(a) : "l"(p));
    return a;
}

#define CP_ASYNC16(dst, src) \
    asm volatile("cp.async.cg.shared.global [%0], [%1], 16;" \
                 :: "r"(dst), "l"(src) : "memory")
#define CP_COMMIT() asm volatile("cp.async.commit_group;" ::: "memory")
#define CP_WAIT(n)  asm volatile("cp.async.wait_group %0;" :: "n"(n) : "memory")

__device__ __forceinline__ void ldm_x4(uint32_t a, uint32_t r[4]) {
    asm volatile("ldmatrix.sync.aligned.m8n8.x4.shared.b16 {%0,%1,%2,%3}, [%4];"
                 : "=r"(r[0]), "=r"(r[1]), "=r"(r[2]), "=r"(r[3]) : "r"(a));
}
__device__ __forceinline__ void ldm_x2(uint32_t a, uint32_t r[2]) {
    asm volatile("ldmatrix.sync.aligned.m8n8.x2.shared.b16 {%0,%1}, [%2];"
                 : "=r"(r[0]), "=r"(r[1]) : "r"(a));
}
__device__ __forceinline__ void mma16816(float c[4], const uint32_t a[4],
                                         const uint32_t b[2]) {
    asm volatile(
        "mma.sync.aligned.m16n8k16.row.col.f32.bf16.bf16.f32 "
        "{%0,%1,%2,%3}, {%4,%5,%6,%7}, {%8,%9}, {%0,%1,%2,%3};"
        : "+f"(c[0]), "+f"(c[1]), "+f"(c[2]), "+f"(c[3])
        : "r"(a[0]), "r"(a[1]), "r"(a[2]), "r"(a[3]), "r"(b[0]), "r"(b[1]));
}

__device__ __forceinline__ void split2(float x, __nv_bfloat16& h, __nv_bfloat16& l) {
    h = __float2bfloat16(x);
    l = __float2bfloat16(x - __bfloat162float(h));
}

// ---------------------------------------------------------------------------
// fp32 -> bf16 hi/lo split (weights prepass).
// ---------------------------------------------------------------------------
__global__ void __launch_bounds__(256) cvt_kernel(
    const float* __restrict__ s, __nv_bfloat16* __restrict__ hi,
    __nv_bfloat16* __restrict__ lo, int n4)
{
    int i = blockIdx.x * 256 + threadIdx.x;
    if (i >= n4) return;
    float4 v = ((const float4*)s)[i];
    __nv_bfloat16 h0, l0, h1, l1, h2, l2, h3, l3;
    split2(v.x, h0, l0); split2(v.y, h1, l1);
    split2(v.z, h2, l2); split2(v.w, h3, l3);
    ((__nv_bfloat162*)hi)[2 * i]     = __halves2bfloat162(h0, h1);
    ((__nv_bfloat162*)hi)[2 * i + 1] = __halves2bfloat162(h2, h3);
    ((__nv_bfloat162*)lo)[2 * i]     = __halves2bfloat162(l0, l1);
    ((__nv_bfloat162*)lo)[2 * i + 1] = __halves2bfloat162(l2, l3);
}

// ---------------------------------------------------------------------------
// LayerNorm -> bf16 hi/lo.
// ---------------------------------------------------------------------------
__global__ void __launch_bounds__(256) ln_kernel(
    const float* __restrict__ x, const float* __restrict__ gma,
    const float* __restrict__ bta, __nv_bfloat16* __restrict__ oh,
    __nv_bfloat16* __restrict__ ol)
{
    int row = blockIdx.x;
    const float* xr = x + (size_t)row * D_;
    int t = threadIdx.x;

    float v0 = xr[t], v1 = xr[t + 256], v2 = xr[t + 512];
    float s  = v0 + v1 + v2;
    float s2 = v0 * v0 + v1 * v1 + v2 * v2;
#pragma unroll
    for (int m = 16; m; m >>= 1) {
        s  += __shfl_xor_sync(0xffffffffu, s,  m);
        s2 += __shfl_xor_sync(0xffffffffu, s2, m);
    }
    __shared__ float ws[8], ws2[8], stat[2];
    int w = t >> 5;
    if ((t & 31) == 0) { ws[w] = s; ws2[w] = s2; }
    __syncthreads();
    if (t == 0) {
        float a = 0.f, a2 = 0.f;
#pragma unroll
        for (int i = 0; i < 8; i++) { a += ws[i]; a2 += ws2[i]; }
        float mu  = a * (1.0f / D_);
        float var = a2 * (1.0f / D_) - mu * mu;
        stat[0] = mu;
        stat[1] = rsqrtf(var + 1e-5f);
    }
    __syncthreads();
    float mu = stat[0], rs = stat[1];
    size_t base = (size_t)row * D_;
#pragma unroll
    for (int e = 0; e < 3; e++) {
        int idx = t + e * 256;
        float v = (e == 0) ? v0 : (e == 1) ? v1 : v2;
        float y = (v - mu) * rs * gma[idx] + bta[idx];
        __nv_bfloat16 h, l;
        split2(y, h, l);
        oh[base + idx] = h;
        ol[base + idx] = l;
    }
}

// ---------------------------------------------------------------------------
// mma.sync GEMM: C[M,N] = A @ B^T, 3-term bf16 split folded into K (K' = 3K).
//   128x128 CTA tile, BK=32, 4-stage cp.async pipeline, 8 warps (2x4),
//   each warp 64x32 output via m16n8k16 bf16 MMA, fp32 accumulate.
//   MODE 0: C = acc + bias (fp32)
//   MODE 1: C = acc + bias + res (fp32)
//   MODE 2: Ch/Cl = split(QuickGELU(acc + bias)) (bf16 hi/lo)
// ---------------------------------------------------------------------------
template <int MODE>
__global__ void __launch_bounds__(256) tgemm(
    const __nv_bfloat16* __restrict__ Ah, const __nv_bfloat16* __restrict__ Al,
    const __nv_bfloat16* __restrict__ Bh, const __nv_bfloat16* __restrict__ Bl,
    const float* __restrict__ bias, const float* __restrict__ res,
    float* __restrict__ C, __nv_bfloat16* __restrict__ Ch,
    __nv_bfloat16* __restrict__ Cl, int Ndim, int K)
{
    extern __shared__ char sm[];
    uint32_t sb = smem_u32(sm);
    int t = threadIdx.x, w = t >> 5, l = t & 31;
    int col0 = blockIdx.x * BN;
    int row0 = blockIdx.y * BM;
    int kc = K >> 5;         // 32-wide chunks per term
    int nt = 3 * kc;

    int wm = (w >> 2) * 64;  // warp M offset in tile
    int wn = (w & 3) * 32;   // warp N offset in tile

    float acc[4][4][4];
#pragma unroll
    for (int i = 0; i < 4; i++)
#pragma unroll
        for (int j = 0; j < 4; j++)
#pragma unroll
            for (int q = 0; q < 4; q++) acc[i][j][q] = 0.f;

    // Per-thread load assignment: 2 chunks of A + 2 of B (16B each).
    int ch0 = t, ch1 = t + 256;            // chunk ids 0..511
    int ra0 = ch0 >> 2, ca0 = (ch0 & 3);   // row, 16B-chunk within row
    int ra1 = ch1 >> 2, ca1 = (ch1 & 3);

#define ISSUE_TILE(tile)                                                        \
    do {                                                                        \
        int _term = (tile) / kc;                                                \
        int _kk = ((tile) - _term * kc) << 5;                                   \
        const __nv_bfloat16* _As = (_term == 1) ? Al : Ah;                      \
        const __nv_bfloat16* _Bs = (_term == 2) ? Bl : Bh;                      \
        uint32_t _st = sb + ((tile) % STAGES) * STAGE_BYTES;                    \
        CP_ASYNC16(_st + ra0 * ROWB + ca0 * 16,                                 \
                   _As + (size_t)(row0 + ra0) * K + _kk + ca0 * 8);             \
        CP_ASYNC16(_st + ra1 * ROWB + ca1 * 16,                                 \
                   _As + (size_t)(row0 + ra1) * K + _kk + ca1 * 8);             \
        CP_ASYNC16(_st + TILE_A + ra0 * ROWB + ca0 * 16,                        \
                   _Bs + (size_t)(col0 + ra0) * K + _kk + ca0 * 8);             \
        CP_ASYNC16(_st + TILE_A + ra1 * ROWB + ca1 * 16,                        \
                   _Bs + (size_t)(col0 + ra1) * K + _kk + ca1 * 8);             \
        CP_COMMIT();                                                            \
    } while (0)

#pragma unroll
    for (int s = 0; s < STAGES - 1; s++) ISSUE_TILE(s);

    for (int tile = 0; tile < nt; tile++) {
        CP_WAIT(STAGES - 2);
        __syncthreads();
        uint32_t st = sb + (tile % STAGES) * STAGE_BYTES;

#pragma unroll
        for (int ks = 0; ks < 2; ks++) {
            uint32_t a[4][4], b[4][2];
#pragma unroll
            for (int fm = 0; fm < 4; fm++) {
                uint32_t addr = st + (wm + fm * 16 + (l & 15)) * ROWB
                                + (ks * 16 + (l >> 4) * 8) * 2;
                ldm_x4(addr, a[fm]);
            }
#pragma unroll
            for (int fn = 0; fn < 4; fn++) {
                uint32_t addr = st + TILE_A + (wn + fn * 8 + (l & 7)) * ROWB
                                + (ks * 16 + ((l >> 3) & 1) * 8) * 2;
                ldm_x2(addr, b[fn]);
            }
#pragma unroll
            for (int fm = 0; fm < 4; fm++)
#pragma unroll
                for (int fn = 0; fn < 4; fn++)
                    mma16816(acc[fm][fn], a[fm], b[fn]);
        }

        __syncthreads();
        if (tile + STAGES - 1 < nt) ISSUE_TILE(tile + STAGES - 1);
        else CP_COMMIT();   // keep group count in lockstep for CP_WAIT
    }
#undef ISSUE_TILE

    // Epilogue: acc[fm][fn][{c0,c1,c2,c3}] -> rows (grp, grp+8), cols (2*tig,+1)
    int grp = l >> 2, tig = l & 3;
#pragma unroll
    for (int fm = 0; fm < 4; fm++) {
#pragma unroll
        for (int fn = 0; fn < 4; fn++) {
            int col = col0 + wn + fn * 8 + tig * 2;
            float b0 = bias[col], b1 = bias[col + 1];
#pragma unroll
            for (int h = 0; h < 2; h++) {
                int row = row0 + wm + fm * 16 + grp + h * 8;
                size_t off = (size_t)row * Ndim + col;
                float v0 = acc[fm][fn][h * 2 + 0] + b0;
                float v1 = acc[fm][fn][h * 2 + 1] + b1;
                if (MODE == 1) {
                    float2 rv = *(const float2*)(res + off);
                    v0 += rv.x; v1 += rv.y;
                }
                if (MODE == 2) {
                    v0 = v0 / (1.f + __expf(-1.702f * v0));
                    v1 = v1 / (1.f + __expf(-1.702f * v1));
                    __nv_bfloat16 h0, l0, h1, l1;
                    split2(v0, h0, l0); split2(v1, h1, l1);
                    *(__nv_bfloat162*)(Ch + off) = __halves2bfloat162(h0, h1);
                    *(__nv_bfloat162*)(Cl + off) = __halves2bfloat162(l0, l1);
                } else {
                    *(float2*)(C + off) = make_float2(v0, v1);
                }
            }
        }
    }
}

// ---------------------------------------------------------------------------
// Flash attention (fp32), prompt-prefixed KV. Output -> bf16 hi/lo.
// ---------------------------------------------------------------------------
__global__ void __launch_bounds__(256) attn_kernel(
    const float* __restrict__ qkv, const float* __restrict__ prompt,
    __nv_bfloat16* __restrict__ oh, __nv_bfloat16* __restrict__ ol)
{
    extern __shared__ float sm_attn[];
    float* Qs = sm_attn;
    float* Ks = sm_attn + 4096;
    float* Vs = sm_attn + 4096 + 4160;
    float* Ps = sm_attn + 4096 + 2 * 4160;

    int q0 = blockIdx.x * 64;
    int h  = blockIdx.y;
    int b  = blockIdx.z;
    int t  = threadIdx.x;
    int rg = t >> 4;
    int cg = t & 15;

    for (int i = t; i < 1024; i += 256) {
        int r  = i >> 4;
        int d4 = (i & 15) * 4;
        float4 v = *(const float4*)(qkv + (size_t)(b * N_ + q0 + r) * (3 * D_) + h * 64 + d4);
        *(float4*)&Qs[r * 64 + d4] = v;
    }

    float m_i[4], l_i[4], O[4][4];
#pragma unroll
    for (int i = 0; i < 4; i++) {
        m_i[i] = -1e30f; l_i[i] = 0.f;
#pragma unroll
        for (int j = 0; j < 4; j++) O[i][j] = 0.f;
    }

    for (int kt = 0; kt < 17; kt++) {
        int j0 = kt * 64;
        for (int i = t; i < 1024; i += 256) {
            int r  = i >> 4;
            int d4 = (i & 15) * 4;
            int j  = j0 + r;
            float4 kv, vv;
            if (j < P_) {
                const float* pb = prompt + ((((size_t)b * 2 + 0) * P_ + j) * H_ + h) * 64 + d4;
                kv = *(const float4*)pb;
                vv = *(const float4*)(pb + (size_t)P_ * H_ * 64);
            } else if (j < KVLEN_) {
                const float* base = qkv + (size_t)(b * N_ + (j - P_)) * (3 * D_) + h * 64 + d4;
                kv = *(const float4*)(base + D_);
                vv = *(const float4*)(base + 2 * D_);
            } else {
                kv = make_float4(0.f, 0.f, 0.f, 0.f);
                vv = kv;
            }
            Ks[r * 65 + d4 + 0] = kv.x; Ks[r * 65 + d4 + 1] = kv.y;
            Ks[r * 65 + d4 + 2] = kv.z; Ks[r * 65 + d4 + 3] = kv.w;
            Vs[r * 65 + d4 + 0] = vv.x; Vs[r * 65 + d4 + 1] = vv.y;
            Vs[r * 65 + d4 + 2] = vv.z; Vs[r * 65 + d4 + 3] = vv.w;
        }
        __syncthreads();

        float s[4][4];
#pragma unroll
        for (int i = 0; i < 4; i++)
#pragma unroll
            for (int j = 0; j < 4; j++) s[i][j] = 0.f;

        for (int d = 0; d < 64; d++) {
            float qv[4], kv[4];
#pragma unroll
            for (int i = 0; i < 4; i++) qv[i] = Qs[(rg * 4 + i) * 64 + d];
#pragma unroll
            for (int j = 0; j < 4; j++) kv[j] = Ks[(cg * 4 + j) * 65 + d];
#pragma unroll
            for (int i = 0; i < 4; i++)
#pragma unroll
                for (int j = 0; j < 4; j++)
                    s[i][j] += qv[i] * kv[j];
        }

#pragma unroll
        for (int i = 0; i < 4; i++) {
#pragma unroll
            for (int j = 0; j < 4; j++)
                s[i][j] = (j0 + cg * 4 + j < KVLEN_) ? s[i][j] * 0.125f : -1e30f;

            float mx = fmaxf(fmaxf(s[i][0], s[i][1]), fmaxf(s[i][2], s[i][3]));
#pragma unroll
            for (int msk = 1; msk < 16; msk <<= 1)
                mx = fmaxf(mx, __shfl_xor_sync(0xffffffffu, mx, msk));

            float mn   = fmaxf(m_i[i], mx);
            float corr = expf(m_i[i] - mn);
            float ps   = 0.f;
#pragma unroll
            for (int j = 0; j < 4; j++) {
                float p = expf(s[i][j] - mn);
                s[i][j] = p;
                ps += p;
            }
#pragma unroll
            for (int msk = 1; msk < 16; msk <<= 1)
                ps += __shfl_xor_sync(0xffffffffu, ps, msk);

            l_i[i] = l_i[i] * corr + ps;
            m_i[i] = mn;
#pragma unroll
            for (int j = 0; j < 4; j++) O[i][j] *= corr;
        }

#pragma unroll
        for (int i = 0; i < 4; i++)
#pragma unroll
            for (int j = 0; j < 4; j++)
                Ps[(rg * 4 + i) * 65 + cg * 4 + j] = s[i][j];
        __syncthreads();

        for (int k = 0; k < 64; k++) {
            float pv[4], vv[4];
#pragma unroll
            for (int i = 0; i < 4; i++) pv[i] = Ps[(rg * 4 + i) * 65 + k];
#pragma unroll
            for (int j = 0; j < 4; j++) vv[j] = Vs[k * 65 + cg * 4 + j];
#pragma unroll
            for (int i = 0; i < 4; i++)
#pragma unroll
                for (int j = 0; j < 4; j++)
                    O[i][j] += pv[i] * vv[j];
        }
        __syncthreads();
    }

#pragma unroll
    for (int i = 0; i < 4; i++) {
        float inv = 1.f / l_i[i];
        int r = q0 + rg * 4 + i;
        size_t base = (size_t)(b * N_ + r) * D_ + h * 64 + cg * 4;
        __nv_bfloat16 h0, l0, h1, l1, h2, l2, h3, l3;
        split2(O[i][0] * inv, h0, l0); split2(O[i][1] * inv, h1, l1);
        split2(O[i][2] * inv, h2, l2); split2(O[i][3] * inv, h3, l3);
        ((__nv_bfloat162*)(oh + base))[0] = __halves2bfloat162(h0, h1);
        ((__nv_bfloat162*)(oh + base))[1] = __halves2bfloat162(h2, h3);
        ((__nv_bfloat162*)(ol + base))[0] = __halves2bfloat162(l0, l1);
        ((__nv_bfloat162*)(ol + base))[1] = __halves2bfloat162(l2, l3);
    }
}

// ---------------------------------------------------------------------------
// Launch pipeline (graph-capturable).
// ---------------------------------------------------------------------------
extern "C" void kernel_launch(void* const* d_in, const int* in_sizes, int n_in,
                              void* d_out, int out_size)
{
    const float* x      = (const float*)d_in[0];
    const float* prompt = (const float*)d_in[1];
    const float* qkv_w  = (const float*)d_in[2];
    const float* qkv_b  = (const float*)d_in[3];
    const float* out_w  = (const float*)d_in[4];
    const float* out_b  = (const float*)d_in[5];
    const float* ln1_g  = (const float*)d_in[6];
    const float* ln1_b  = (const float*)d_in[7];
    const float* ln2_g  = (const float*)d_in[8];
    const float* ln2_b  = (const float*)d_in[9];
    const float* fc1_w  = (const float*)d_in[10];
    const float* fc1_b  = (const float*)d_in[11];
    const float* fc2_w  = (const float*)d_in[12];
    const float* fc2_b  = (const float*)d_in[13];
    float* out = (float*)d_out;

    void* p;
    cudaGetSymbolAddress(&p, g_hh);  __nv_bfloat16* hh  = (__nv_bfloat16*)p;
    cudaGetSymbolAddress(&p, g_hl);  __nv_bfloat16* hl  = (__nv_bfloat16*)p;
    cudaGetSymbolAddress(&p, g_qkv); float* qkvbuf      = (float*)p;
    cudaGetSymbolAddress(&p, g_oh);  __nv_bfloat16* oh  = (__nv_bfloat16*)p;
    cudaGetSymbolAddress(&p, g_ol);  __nv_bfloat16* ol  = (__nv_bfloat16*)p;
    cudaGetSymbolAddress(&p, g_x1);  float* x1buf       = (float*)p;
    cudaGetSymbolAddress(&p, g_mh);  __nv_bfloat16* mh  = (__nv_bfloat16*)p;
    cudaGetSymbolAddress(&p, g_ml);  __nv_bfloat16* ml  = (__nv_bfloat16*)p;
    cudaGetSymbolAddress(&p, g_w1h); __nv_bfloat16* w1h = (__nv_bfloat16*)p;
    cudaGetSymbolAddress(&p, g_w1l); __nv_bfloat16* w1l = (__nv_bfloat16*)p;
    cudaGetSymbolAddress(&p, g_w2h); __nv_bfloat16* w2h = (__nv_bfloat16*)p;
    cudaGetSymbolAddress(&p, g_w2l); __nv_bfloat16* w2l = (__nv_bfloat16*)p;
    cudaGetSymbolAddress(&p, g_w3h); __nv_bfloat16* w3h = (__nv_bfloat16*)p;
    cudaGetSymbolAddress(&p, g_w3l); __nv_bfloat16* w3l = (__nv_bfloat16*)p;
    cudaGetSymbolAddress(&p, g_w4h); __nv_bfloat16* w4h = (__nv_bfloat16*)p;
    cudaGetSymbolAddress(&p, g_w4l); __nv_bfloat16* w4l = (__nv_bfloat16*)p;

    cudaFuncSetAttribute(tgemm<0>, cudaFuncAttributeMaxDynamicSharedMemorySize, GEMM_SMEM);
    cudaFuncSetAttribute(tgemm<1>, cudaFuncAttributeMaxDynamicSharedMemorySize, GEMM_SMEM);
    cudaFuncSetAttribute(tgemm<2>, cudaFuncAttributeMaxDynamicSharedMemorySize, GEMM_SMEM);
    cudaFuncSetAttribute(attn_kernel, cudaFuncAttributeMaxDynamicSharedMemorySize, ATTN_SMEM_BYTES);

    // Weight splits.
    cvt_kernel<<<(3 * D_ * D_ / 4 + 255) / 256, 256>>>(qkv_w, w1h, w1l, 3 * D_ * D_ / 4);
    cvt_kernel<<<(D_ * D_ / 4 + 255) / 256, 256>>>(out_w, w2h, w2l, D_ * D_ / 4);
    cvt_kernel<<<(FF_ * D_ / 4 + 255) / 256, 256>>>(fc1_w, w3h, w3l, FF_ * D_ / 4);
    cvt_kernel<<<(D_ * FF_ / 4 + 255) / 256, 256>>>(fc2_w, w4h, w4l, D_ * FF_ / 4);

    // 1. LN1 -> hi/lo
    ln_kernel<<<M_, 256>>>(x, ln1_g, ln1_b, hh, hl);

    // 2. qkv = h @ qkv_w^T + b   [16384 x 2304]
    tgemm<0><<<dim3(3 * D_ / BN, M_ / BM), 256, GEMM_SMEM>>>(
        hh, hl, w1h, w1l, qkv_b, nullptr, qkvbuf, nullptr, nullptr, 3 * D_, D_);

    // 3. attention -> oh/ol
    attn_kernel<<<dim3(N_ / 64, H_, B_), 256, ATTN_SMEM_BYTES>>>(qkvbuf, prompt, oh, ol);

    // 4. x1 = x + o @ out_w^T + b
    tgemm<1><<<dim3(D_ / BN, M_ / BM), 256, GEMM_SMEM>>>(
        oh, ol, w2h, w2l, out_b, x, x1buf, nullptr, nullptr, D_, D_);

    // 5. LN2 -> hi/lo
    ln_kernel<<<M_, 256>>>(x1buf, ln2_g, ln2_b, hh, hl);

    // 6. m = QuickGELU(h @ fc1_w^T + b) -> bf16 hi/lo
    tgemm<2><<<dim3(FF_ / BN, M_ / BM), 256, GEMM_SMEM>>>(
        hh, hl, w3h, w3l, fc1_b, nullptr, nullptr, mh, ml, FF_, D_);

    // 7. out = x1 + m @ fc2_w^T + b
    tgemm<1><<<dim3(D_ / BN, M_ / BM), 256, GEMM_SMEM>>>(
        mh, ml, w4h, w4l, fc2_b, x1buf, out, nullptr, nullptr, D_, FF_);
}